// round 14
// baseline (speedup 1.0000x reference)
#include <cuda_runtime.h>
#include <cuda_fp16.h>
#include <stdint.h>

#define Bc 2
#define Sc 1024
#define Mc 1024
#define Hc 16
#define Kc 2048
#define Rc 4095

// -------- scratch (static device globals; allocation is forbidden) --------
__device__ __half g_clnh[4096 * 1024];   // LN(concat) as fp16 (GEMM A operand)
__device__ float  g_hln [2048 * 1024];   // exact fp32 h_ln (residual)
__device__ __half g_qh  [2048 * 1024];
__device__ __half g_kh  [4096 * 1024];
__device__ __half g_vh  [4096 * 1024];
__device__ __half g_attnh[2048 * 1024];
__device__ __half g_wth [4 * 1024 * 1024]; // Wq,Wk,Wv,Wo transposed [n][k] fp16
__device__ __half g_posh[Bc * Rc * 64];

// ---------------------------------------------------------------------------
__device__ __forceinline__ uint32_t sptr(const void* p) {
    return (uint32_t)__cvta_generic_to_shared(p);
}
__device__ __forceinline__ void ldm4(uint32_t* r, uint32_t a) {
    asm volatile("ldmatrix.sync.aligned.m8n8.x4.shared.b16 {%0,%1,%2,%3},[%4];"
                 : "=r"(r[0]), "=r"(r[1]), "=r"(r[2]), "=r"(r[3]) : "r"(a));
}
__device__ __forceinline__ void ldm4t(uint32_t* r, uint32_t a) {
    asm volatile("ldmatrix.sync.aligned.m8n8.x4.trans.shared.b16 {%0,%1,%2,%3},[%4];"
                 : "=r"(r[0]), "=r"(r[1]), "=r"(r[2]), "=r"(r[3]) : "r"(a));
}
__device__ __forceinline__ void mma16(float* d, const uint32_t* a,
                                      uint32_t b0, uint32_t b1) {
    asm volatile(
        "mma.sync.aligned.m16n8k16.row.col.f32.f16.f16.f32 "
        "{%0,%1,%2,%3},{%4,%5,%6,%7},{%8,%9},{%0,%1,%2,%3};"
        : "+f"(d[0]), "+f"(d[1]), "+f"(d[2]), "+f"(d[3])
        : "r"(a[0]), "r"(a[1]), "r"(a[2]), "r"(a[3]), "r"(b0), "r"(b1));
}
__device__ __forceinline__ void cpa(uint32_t d, const void* s) {
    asm volatile("cp.async.cg.shared.global [%0], [%1], 16;" :: "r"(d), "l"(s));
}
#define CP_COMMIT asm volatile("cp.async.commit_group;")
#define CP_WAIT(n) asm volatile("cp.async.wait_group %0;" :: "n"(n))

// ---------------------------------------------------------------------------
// Fused pre-pass: blocks [0,4096) weight transpose; [4096,4608) pos convert;
// [4608,8704) layernorm. All 256-thread blocks, one launch.
// ---------------------------------------------------------------------------
__global__ __launch_bounds__(256) void fused_pre(
    const float* __restrict__ hidden, const float* __restrict__ memory,
    const float* __restrict__ gamma, const float* __restrict__ beta,
    const float* __restrict__ Wq, const float* __restrict__ Wk,
    const float* __restrict__ Wv, const float* __restrict__ Wo,
    const float* __restrict__ pos_emb) {
    int bid = blockIdx.x, t = threadIdx.x;

    if (bid < 4096) {  // ---- weight transpose + fp16
        __shared__ float tile[32][33];
        int z = bid >> 10, m = bid & 1023;
        const float* W = (z == 0) ? Wq : (z == 1) ? Wk : (z == 2) ? Wv : Wo;
        __half* Wt = g_wth + (size_t)z * 1024 * 1024;
        int bx = (m & 31) << 5, by = (m >> 5) << 5;
        int tx = t & 31, ty = t >> 5;
#pragma unroll
        for (int i = 0; i < 32; i += 8)
            tile[ty + i][tx] = W[(size_t)(by + ty + i) * 1024 + bx + tx];
        __syncthreads();
#pragma unroll
        for (int i = 0; i < 32; i += 8)
            Wt[(size_t)(bx + ty + i) * 1024 + by + tx] =
                __float2half(tile[tx][ty + i]);
        return;
    }
    if (bid < 4608) {  // ---- pos_emb -> fp16 (vec4)
        int i = (bid - 4096) * 256 + t;   // float4 index
        if (i < (Bc * Rc * 64) / 4) {
            float4 v = *(const float4*)(pos_emb + ((size_t)i << 2));
            __half2* d = (__half2*)(g_posh + ((size_t)i << 2));
            d[0] = __floats2half2_rn(v.x, v.y);
            d[1] = __floats2half2_rn(v.z, v.w);
        }
        return;
    }
    // ---- layernorm
    int row = bid - 4608;
    int b = row / Kc, r = row % Kc;
    const float* src = (r < Mc) ? (memory + ((size_t)b * Mc + r) * 1024)
                                : (hidden + ((size_t)b * Sc + (r - Mc)) * 1024);
    float4 v = *(const float4*)(src + (t << 2));
    float s = v.x + v.y + v.z + v.w;
    float sq = v.x * v.x + v.y * v.y + v.z * v.z + v.w * v.w;
#pragma unroll
    for (int m = 16; m; m >>= 1) {
        s  += __shfl_xor_sync(0xffffffffu, s, m);
        sq += __shfl_xor_sync(0xffffffffu, sq, m);
    }
    __shared__ float ss[8], ssq[8];
    int w = t >> 5, l = t & 31;
    if (l == 0) { ss[w] = s; ssq[w] = sq; }
    __syncthreads();
    if (w == 0) {
        float sv  = (l < 8) ? ss[l]  : 0.f;
        float sqv = (l < 8) ? ssq[l] : 0.f;
#pragma unroll
        for (int m = 4; m; m >>= 1) {
            sv  += __shfl_xor_sync(0xffffffffu, sv, m);
            sqv += __shfl_xor_sync(0xffffffffu, sqv, m);
        }
        if (l == 0) { ss[0] = sv; ssq[0] = sqv; }
    }
    __syncthreads();
    float mean = ss[0] * (1.f / 1024.f);
    float var  = ssq[0] * (1.f / 1024.f) - mean * mean;
    float inv  = rsqrtf(var + 1e-5f);
    float4 gv = *(const float4*)(gamma + (t << 2));
    float4 bv = *(const float4*)(beta + (t << 2));
    float o0 = (v.x - mean) * inv * gv.x + bv.x;
    float o1 = (v.y - mean) * inv * gv.y + bv.y;
    float o2 = (v.z - mean) * inv * gv.z + bv.z;
    float o3 = (v.w - mean) * inv * gv.w + bv.w;
    __half2* dsth = (__half2*)(g_clnh + (size_t)row * 1024) + (t << 1);
    dsth[0] = __floats2half2_rn(o0, o1);
    dsth[1] = __floats2half2_rn(o2, o3);
    if (r >= Mc) {
        *(float4*)(g_hln + ((size_t)b * Sc + (r - Mc)) * 1024 + (t << 2)) =
            make_float4(o0, o1, o2, o3);
    }
}

// ---------------------------------------------------------------------------
// fp16 GEMM body: C[128 x NC] = A[128x1024] @ Wt[NC x 1024]^T, BK=64,
// NC = NPW*32 (NPW=4 -> 128 cols, NPW=2 -> 64 cols).
// 3-stage ring / prefill 2 / ONE syncthreads per iter. 256 threads, 8 warps.
// ---------------------------------------------------------------------------
#define GASZ (128 * 72)

template <int MODE, int NPW>
__device__ __forceinline__ void gemm_body(const __half* __restrict__ A,
                                          const __half* __restrict__ Wt,
                                          __half* __restrict__ Ch,
                                          float* __restrict__ Cf,
                                          const float* __restrict__ res,
                                          __half* sm) {
    const int NC = NPW * 32;
    const int BSZ = NC * 72;
    const int STG = GASZ + BSZ;
    int t = threadIdx.x, lane = t & 31, w = t >> 5;
    int wm = (w >> 1) << 5, wn = (w & 1) * (NPW * 16);

    auto load_stage = [&](int ki) {
        __half* As = sm + (ki % 3) * STG;
        __half* Bs = As + GASZ;
        int k0 = ki << 6;
#pragma unroll
        for (int it = 0; it < 4; it++) {
            int e = t + (it << 8);
            int r = e >> 3, c = e & 7;
            cpa(sptr(As + r * 72 + (c << 3)), A + (size_t)r * 1024 + k0 + (c << 3));
        }
#pragma unroll
        for (int it = 0; it < NPW; it++) {
            int e = t + (it << 8);
            int r = e >> 3, c = e & 7;
            cpa(sptr(Bs + r * 72 + (c << 3)), Wt + (size_t)r * 1024 + k0 + (c << 3));
        }
    };

    load_stage(0); CP_COMMIT;
    load_stage(1); CP_COMMIT;

    float acc[2][2 * NPW][4];
#pragma unroll
    for (int mt = 0; mt < 2; mt++)
#pragma unroll
        for (int nt = 0; nt < 2 * NPW; nt++)
#pragma unroll
            for (int i = 0; i < 4; i++) acc[mt][nt][i] = 0.f;

    for (int i = 0; i < 16; i++) {
        CP_WAIT(1);
        __syncthreads();
        if (i + 2 < 16) load_stage(i + 2);
        CP_COMMIT;
        __half* As = sm + (i % 3) * STG;
        __half* Bs = As + GASZ;
#pragma unroll
        for (int kc = 0; kc < 4; kc++) {
            uint32_t am[2][4];
#pragma unroll
            for (int mt = 0; mt < 2; mt++)
                ldm4(am[mt], sptr(As + (wm + mt * 16 + (lane & 15)) * 72 +
                                  (kc << 4) + ((lane >> 4) << 3)));
#pragma unroll
            for (int np = 0; np < NPW; np++) {
                uint32_t bb[4];
                ldm4(bb, sptr(Bs + (wn + (np << 4) + (lane & 7) + ((lane >> 4) << 3)) * 72 +
                              (kc << 4) + (((lane >> 3) & 1) << 3)));
                mma16(acc[0][np * 2],     am[0], bb[0], bb[1]);
                mma16(acc[0][np * 2 + 1], am[0], bb[2], bb[3]);
                mma16(acc[1][np * 2],     am[1], bb[0], bb[1]);
                mma16(acc[1][np * 2 + 1], am[1], bb[2], bb[3]);
            }
        }
    }

    int R = lane >> 2, c2 = (lane & 3) << 1;
#pragma unroll
    for (int mt = 0; mt < 2; mt++) {
        int r0 = wm + mt * 16 + R, r1 = r0 + 8;
#pragma unroll
        for (int nt = 0; nt < 2 * NPW; nt++) {
            int c = wn + (nt << 3) + c2;
            if (MODE == 0) {
                *(__half2*)(Ch + (size_t)r0 * 1024 + c) =
                    __floats2half2_rn(acc[mt][nt][0], acc[mt][nt][1]);
                *(__half2*)(Ch + (size_t)r1 * 1024 + c) =
                    __floats2half2_rn(acc[mt][nt][2], acc[mt][nt][3]);
            } else {
                const float* rs0 = res + (size_t)r0 * 1024 + c;
                const float* rs1 = res + (size_t)r1 * 1024 + c;
                Cf[(size_t)r0 * 1024 + c]     = acc[mt][nt][0] + rs0[0];
                Cf[(size_t)r0 * 1024 + c + 1] = acc[mt][nt][1] + rs0[1];
                Cf[(size_t)r1 * 1024 + c]     = acc[mt][nt][2] + rs1[0];
                Cf[(size_t)r1 * 1024 + c + 1] = acc[mt][nt][3] + rs1[1];
            }
        }
    }
}

#define PROJ_SMEM_BYTES (3 * (GASZ + 128 * 72) * 2)
#define OUT_SMEM_BYTES  (3 * (GASZ + 64 * 72) * 2)

// Fused Q/K/V projection: grid (8, 80); y: [0,32) K, [32,64) V, [64,80) Q
__global__ __launch_bounds__(256, 2) void proj_tc() {
    extern __shared__ __align__(16) __half smh[];
    int y = blockIdx.y, col0 = blockIdx.x << 7;
    const __half* A;
    const __half* Wt;
    __half* Cb;
    if (y < 32) {
        A = g_clnh + (size_t)(y << 7) * 1024;
        Wt = g_wth + (1u << 20) + (size_t)col0 * 1024;
        Cb = g_kh + (size_t)(y << 7) * 1024 + col0;
    } else if (y < 64) {
        int yy = y - 32;
        A = g_clnh + (size_t)(yy << 7) * 1024;
        Wt = g_wth + (2u << 20) + (size_t)col0 * 1024;
        Cb = g_vh + (size_t)(yy << 7) * 1024 + col0;
    } else {
        int yy = y - 64;
        int b = yy >> 3, r0 = (yy & 7) << 7;
        A = g_clnh + ((size_t)(b * Kc + Mc) + r0) * 1024;
        Wt = g_wth + (size_t)col0 * 1024;
        Cb = g_qh + ((size_t)(b * Sc) + r0) * 1024 + col0;
    }
    gemm_body<0, 4>(A, Wt, Cb, nullptr, nullptr, smh);
}

// Output projection + residual: grid (16, 16), 128x64 tiles
__global__ __launch_bounds__(256, 2) void out_tc(float* __restrict__ out) {
    extern __shared__ __align__(16) __half smh[];
    int col0 = blockIdx.x << 6, row0 = blockIdx.y << 7;
    const __half* A = g_attnh + (size_t)row0 * 1024;
    const __half* Wt = g_wth + (3u << 20) + (size_t)col0 * 1024;
    const float* res = g_hln + (size_t)row0 * 1024 + col0;
    float* Cf = out + (size_t)row0 * 1024 + col0;
    gemm_body<1, 2>(A, Wt, nullptr, Cf, res, smh);
}

// ---------------------------------------------------------------------------
// fp16 flash attention — R12 protocol at 72KB smem -> 3 CTAs/SM (12 warps).
// 128 threads / 4 warps / 64 query rows; K,V double-buffered; pos pages
// 2-ring; fp16 qpos band ring (2 slots); Q staged through Vbuf[1];
// P kept in registers for PV. ONE wait + ONE sync per k-tile (R12-identical).
// ---------------------------------------------------------------------------
#define AB_K0 0
#define AB_K1 9216
#define AB_V0 18432
#define AB_V1 27648
#define AB_P0 36864
#define AB_P1 46080
#define AB_QS 55296
#define ATTN_SMEM_BYTES (AB_QS + 2 * 64 * 72 * 2)   // 73728 = 72KB

__global__ __launch_bounds__(128, 3) void attn_tc() {
    extern __shared__ __align__(16) char smb[];
    __half* Kbuf[2] = {(__half*)(smb + AB_K0), (__half*)(smb + AB_K1)};
    __half* Vbuf[2] = {(__half*)(smb + AB_V0), (__half*)(smb + AB_V1)};
    __half* Pp[2] = {(__half*)(smb + AB_P0), (__half*)(smb + AB_P1)};
    __half* Qs[2] = {(__half*)(smb + AB_QS), (__half*)(smb + AB_QS + 9216)};

    int t = threadIdx.x, lane = t & 31, w = t >> 5;
    int R = lane >> 2, c2 = (lane & 3) << 1;
    int qi = 15 - (int)blockIdx.x;
    int s0 = qi << 6;
    int bh = blockIdx.y, b = bh >> 4, h = bh & 15;

    const __half* qbase = g_qh + ((size_t)(b * Sc + s0)) * 1024 + h * 64;
    const __half* kbase = g_kh + ((size_t)b * Kc) * 1024 + h * 64;
    const __half* vbase = g_vh + ((size_t)b * Kc) * 1024 + h * 64;
    const __half* pbase = g_posh + (size_t)b * Rc * 64;
    int rr0base = 960 - s0;
    int ntiles = qi + 17;
    int dq0 = w * 16 + R, dq1 = dq0 + 8;

    // ---- prologue G1: Q staged into Vbuf[1] (free until tile-0 prefetch)
    for (int e = t; e < 512; e += 128) {
        int r = e >> 3, c = e & 7;
        cpa(sptr(Vbuf[1] + r * 72 + (c << 3)), qbase + (size_t)r * 1024 + (c << 3));
    }
    CP_COMMIT;
    // ---- prologue G2: pos pages 0+1, K0, V0
    for (int e = t; e < 512; e += 128) {
        int r = e >> 3, c = e & 7;
        cpa(sptr(Pp[0] + r * 72 + (c << 3)),
            pbase + (size_t)(rr0base + r) * 64 + (c << 3));
        cpa(sptr(Pp[1] + r * 72 + (c << 3)),
            pbase + (size_t)(rr0base + 64 + r) * 64 + (c << 3));
        cpa(sptr(Kbuf[0] + r * 72 + (c << 3)), kbase + (size_t)r * 1024 + (c << 3));
        cpa(sptr(Vbuf[0] + r * 72 + (c << 3)), vbase + (size_t)r * 1024 + (c << 3));
    }
    CP_COMMIT;

    CP_WAIT(1);          // Q ready
    __syncthreads();
    uint32_t qf[4][4];
#pragma unroll
    for (int kc = 0; kc < 4; kc++)
        ldm4(qf[kc], sptr(Vbuf[1] + (w * 16 + (lane & 15)) * 72 +
                          (kc << 4) + ((lane >> 4) << 3)));

    // qpos helper: Q @ pos_page^T (64x64) -> fp16 band slot (warp-local rows)
    auto qpos_page = [&](const __half* page, __half* dst) {
#pragma unroll
        for (int np = 0; np < 4; np++) {
            float qa0[4] = {0.f, 0.f, 0.f, 0.f}, qa1[4] = {0.f, 0.f, 0.f, 0.f};
#pragma unroll
            for (int kc = 0; kc < 4; kc++) {
                uint32_t bb[4];
                ldm4(bb, sptr(page + ((np << 4) + (lane & 7) + ((lane >> 4) << 3)) * 72 +
                              (kc << 4) + (((lane >> 3) & 1) << 3)));
                mma16(qa0, qf[kc], bb[0], bb[1]);
                mma16(qa1, qf[kc], bb[2], bb[3]);
            }
            __half* q0 = dst + dq0 * 72 + (np << 4);
            __half* q1 = dst + dq1 * 72 + (np << 4);
            *(__half2*)(q0 + c2)     = __floats2half2_rn(qa0[0], qa0[1]);
            *(__half2*)(q1 + c2)     = __floats2half2_rn(qa0[2], qa0[3]);
            *(__half2*)(q0 + 8 + c2) = __floats2half2_rn(qa1[0], qa1[1]);
            *(__half2*)(q1 + 8 + c2) = __floats2half2_rn(qa1[2], qa1[3]);
        }
    };

    CP_WAIT(0);          // pos/K/V ready
    __syncthreads();
    qpos_page(Pp[0], Qs[0]);
    __syncthreads();     // all warps done reading Pp[0] before tile-0 prefetch

    float O[8][4];
#pragma unroll
    for (int nt = 0; nt < 8; nt++)
#pragma unroll
        for (int i = 0; i < 4; i++) O[nt][i] = 0.f;
    float m0 = -1e30f, m1 = -1e30f, l0 = 0.f, l1 = 0.f;

    for (int kt = 0; kt < ntiles; kt++) {
        int k0 = kt << 6;
        const __half* QpL = Qs[kt & 1];
        __half* QpH = Qs[(kt + 1) & 1];
        __half* Ks = Kbuf[kt & 1];
        __half* Vs = Vbuf[kt & 1];

        if (kt) { CP_WAIT(0); __syncthreads(); }

        // prefetch tile kt+1: pos page kt+2 -> Pp[kt&1], K(kt+1), V(kt+1)
        if (kt + 1 < ntiles) {
            __half* Pn = Pp[kt & 1];
            __half* Kn = Kbuf[(kt + 1) & 1];
            __half* Vn = Vbuf[(kt + 1) & 1];
            int gp = rr0base + k0 + 128;
            int gk = k0 + 64;
            for (int e = t; e < 512; e += 128) {
                int r = e >> 3, c = e & 7;
                cpa(sptr(Pn + r * 72 + (c << 3)),
                    pbase + (size_t)(gp + r) * 64 + (c << 3));
                cpa(sptr(Kn + r * 72 + (c << 3)),
                    kbase + (size_t)(gk + r) * 1024 + (c << 3));
                cpa(sptr(Vn + r * 72 + (c << 3)),
                    vbase + (size_t)(gk + r) * 1024 + (c << 3));
            }
        }
        CP_COMMIT;

        // ---- fresh qpos: page kt+1 -> band slot (kt+1)&1 (becomes high half)
        qpos_page(Pp[(kt + 1) & 1], QpH);
        __syncwarp();

        // ---- scores = Q @ K^T (64x64)
        float sc[8][4];
#pragma unroll
        for (int nt = 0; nt < 8; nt++)
#pragma unroll
            for (int i = 0; i < 4; i++) sc[nt][i] = 0.f;
#pragma unroll
        for (int np = 0; np < 4; np++) {
            int n0 = np << 4;
#pragma unroll
            for (int kc = 0; kc < 4; kc++) {
                uint32_t bb[4];
                ldm4(bb, sptr(Ks + (n0 + (lane & 7) + ((lane >> 4) << 3)) * 72 +
                              (kc << 4) + (((lane >> 3) & 1) << 3)));
                mma16(sc[np * 2],     qf[kc], bb[0], bb[1]);
                mma16(sc[np * 2 + 1], qf[kc], bb[2], bb[3]);
            }
        }

        // ---- skew add + mask (band col j = dk - dq + 63; L slot j<64)
#pragma unroll
        for (int nt = 0; nt < 8; nt++) {
#pragma unroll
            for (int j = 0; j < 2; j++) {
                int dk = (nt << 3) + c2 + j;
                int j0 = dk - dq0 + 63, j1 = dk - dq1 + 63;
                float p0 = __half2float((j0 < 64) ? QpL[dq0 * 72 + j0]
                                                  : QpH[dq0 * 72 + j0 - 64]);
                float p1 = __half2float((j1 < 64) ? QpL[dq1 * 72 + j1]
                                                  : QpH[dq1 * 72 + j1 - 64]);
                bool mk0 = (k0 + dk) > (s0 + dq0 + Mc);
                bool mk1 = (k0 + dk) > (s0 + dq1 + Mc);
                sc[nt][j]     = mk0 ? -1e30f : (sc[nt][j] + p0) * 0.03125f;
                sc[nt][2 + j] = mk1 ? -1e30f : (sc[nt][2 + j] + p1) * 0.03125f;
            }
        }

        // ---- online softmax; P emitted DIRECTLY into mma A-fragments
        float mx0 = -1e30f, mx1 = -1e30f;
#pragma unroll
        for (int nt = 0; nt < 8; nt++) {
            mx0 = fmaxf(mx0, fmaxf(sc[nt][0], sc[nt][1]));
            mx1 = fmaxf(mx1, fmaxf(sc[nt][2], sc[nt][3]));
        }
        mx0 = fmaxf(mx0, __shfl_xor_sync(0xffffffffu, mx0, 1));
        mx0 = fmaxf(mx0, __shfl_xor_sync(0xffffffffu, mx0, 2));
        mx1 = fmaxf(mx1, __shfl_xor_sync(0xffffffffu, mx1, 1));
        mx1 = fmaxf(mx1, __shfl_xor_sync(0xffffffffu, mx1, 2));
        float mn0 = fmaxf(m0, mx0), mn1 = fmaxf(m1, mx1);
        float al0 = __expf(m0 - mn0), al1 = __expf(m1 - mn1);
        m0 = mn0; m1 = mn1;
        float su0 = 0.f, su1 = 0.f;
        uint32_t ph[4][4];   // P fragments: ph[kc] = A-operand for 16-key block
#pragma unroll
        for (int nt = 0; nt < 8; nt++) {
            float p0 = __expf(sc[nt][0] - mn0), p1 = __expf(sc[nt][1] - mn0);
            float p2 = __expf(sc[nt][2] - mn1), p3 = __expf(sc[nt][3] - mn1);
            su0 += p0 + p1; su1 += p2 + p3;
            __half2 h01 = __floats2half2_rn(p0, p1);
            __half2 h23 = __floats2half2_rn(p2, p3);
            int kc = nt >> 1, hi = (nt & 1) << 1;
            ph[kc][hi]     = *(uint32_t*)&h01;
            ph[kc][hi + 1] = *(uint32_t*)&h23;
        }
        su0 += __shfl_xor_sync(0xffffffffu, su0, 1);
        su0 += __shfl_xor_sync(0xffffffffu, su0, 2);
        su1 += __shfl_xor_sync(0xffffffffu, su1, 1);
        su1 += __shfl_xor_sync(0xffffffffu, su1, 2);
        l0 = l0 * al0 + su0; l1 = l1 * al1 + su1;
#pragma unroll
        for (int nt = 0; nt < 8; nt++) {
            O[nt][0] *= al0; O[nt][1] *= al0;
            O[nt][2] *= al1; O[nt][3] *= al1;
        }

        // ---- O += P @ V  (P from registers; V via ldmatrix.trans)
#pragma unroll
        for (int kc = 0; kc < 4; kc++) {
#pragma unroll
            for (int np = 0; np < 4; np++) {
                uint32_t bb[4];
                ldm4t(bb, sptr(Vs + ((kc << 4) + (lane & 7) + (((lane >> 3) & 1) << 3)) * 72 +
                               (np << 4) + ((lane >> 4) << 3)));
                mma16(O[np * 2],     ph[kc], bb[0], bb[1]);
                mma16(O[np * 2 + 1], ph[kc], bb[2], bb[3]);
            }
        }
    }

    float i0 = 1.f / l0, i1 = 1.f / l1;
    __half* obase = g_attnh + ((size_t)(b * Sc + s0)) * 1024 + h * 64;
#pragma unroll
    for (int nt = 0; nt < 8; nt++) {
        int c = (nt << 3) + c2;
        *(__half2*)(obase + (size_t)dq0 * 1024 + c) =
            __floats2half2_rn(O[nt][0] * i0, O[nt][1] * i0);
        *(__half2*)(obase + (size_t)dq1 * 1024 + c) =
            __floats2half2_rn(O[nt][2] * i1, O[nt][3] * i1);
    }
}

// ---------------------------------------------------------------------------
extern "C" void kernel_launch(void* const* d_in, const int* in_sizes, int n_in,
                              void* d_out, int out_size) {
    const float* hidden  = (const float*)d_in[0];
    const float* pos_emb = (const float*)d_in[1];
    const float* memory  = (const float*)d_in[2];
    // d_in[3] = mask (bool) — recomputed analytically
    const float* Wq = (const float*)d_in[4];
    const float* Wk = (const float*)d_in[5];
    const float* Wv = (const float*)d_in[6];
    const float* Wo = (const float*)d_in[7];
    const float* gamma = (const float*)d_in[8];
    const float* beta  = (const float*)d_in[9];
    float* out = (float*)d_out;

    fused_pre<<<8704, 256>>>(hidden, memory, gamma, beta, Wq, Wk, Wv, Wo,
                             pos_emb);

    cudaFuncSetAttribute(proj_tc, cudaFuncAttributeMaxDynamicSharedMemorySize,
                         PROJ_SMEM_BYTES);
    cudaFuncSetAttribute(out_tc, cudaFuncAttributeMaxDynamicSharedMemorySize,
                         OUT_SMEM_BYTES);
    proj_tc<<<dim3(8, 80), 256, PROJ_SMEM_BYTES>>>();

    cudaFuncSetAttribute(attn_tc, cudaFuncAttributeMaxDynamicSharedMemorySize,
                         ATTN_SMEM_BYTES);
    attn_tc<<<dim3(16, Bc * Hc), 128, ATTN_SMEM_BYTES>>>();

    out_tc<<<dim3(16, 16), 256, OUT_SMEM_BYTES>>>(out);
}

// round 16
// speedup vs baseline: 1.0950x; 1.0950x over previous
#include <cuda_runtime.h>
#include <cuda_fp16.h>
#include <stdint.h>

#define Bc 2
#define Sc 1024
#define Mc 1024
#define Hc 16
#define Kc 2048
#define Rc 4095

// -------- scratch (static device globals; allocation is forbidden) --------
__device__ __half g_clnh[4096 * 1024];   // LN(concat) as fp16 (GEMM A operand)
__device__ float  g_hln [2048 * 1024];   // exact fp32 h_ln (residual)
__device__ __half g_qh  [2048 * 1024];
__device__ __half g_kh  [4096 * 1024];
__device__ __half g_vh  [4096 * 1024];
__device__ __half g_attnh[2048 * 1024];
__device__ __half g_wth [4 * 1024 * 1024]; // Wq,Wk,Wv,Wo transposed [n][k] fp16
__device__ __half g_posh[Bc * Rc * 64];

// ---------------------------------------------------------------------------
__device__ __forceinline__ uint32_t sptr(const void* p) {
    return (uint32_t)__cvta_generic_to_shared(p);
}
__device__ __forceinline__ void ldm4(uint32_t* r, uint32_t a) {
    asm volatile("ldmatrix.sync.aligned.m8n8.x4.shared.b16 {%0,%1,%2,%3},[%4];"
                 : "=r"(r[0]), "=r"(r[1]), "=r"(r[2]), "=r"(r[3]) : "r"(a));
}
__device__ __forceinline__ void ldm4t(uint32_t* r, uint32_t a) {
    asm volatile("ldmatrix.sync.aligned.m8n8.x4.trans.shared.b16 {%0,%1,%2,%3},[%4];"
                 : "=r"(r[0]), "=r"(r[1]), "=r"(r[2]), "=r"(r[3]) : "r"(a));
}
__device__ __forceinline__ void mma16(float* d, const uint32_t* a,
                                      uint32_t b0, uint32_t b1) {
    asm volatile(
        "mma.sync.aligned.m16n8k16.row.col.f32.f16.f16.f32 "
        "{%0,%1,%2,%3},{%4,%5,%6,%7},{%8,%9},{%0,%1,%2,%3};"
        : "+f"(d[0]), "+f"(d[1]), "+f"(d[2]), "+f"(d[3])
        : "r"(a[0]), "r"(a[1]), "r"(a[2]), "r"(a[3]), "r"(b0), "r"(b1));
}
__device__ __forceinline__ void cpa(uint32_t d, const void* s) {
    asm volatile("cp.async.cg.shared.global [%0], [%1], 16;" :: "r"(d), "l"(s));
}
#define CP_COMMIT asm volatile("cp.async.commit_group;")
#define CP_WAIT(n) asm volatile("cp.async.wait_group %0;" :: "n"(n))

// ---------------------------------------------------------------------------
// Fused pre-pass: blocks [0,4096) weight transpose; [4096,4608) pos convert;
// [4608,8704) layernorm. All 256-thread blocks, one launch.
// ---------------------------------------------------------------------------
__global__ __launch_bounds__(256) void fused_pre(
    const float* __restrict__ hidden, const float* __restrict__ memory,
    const float* __restrict__ gamma, const float* __restrict__ beta,
    const float* __restrict__ Wq, const float* __restrict__ Wk,
    const float* __restrict__ Wv, const float* __restrict__ Wo,
    const float* __restrict__ pos_emb) {
    int bid = blockIdx.x, t = threadIdx.x;

    if (bid < 4096) {  // ---- weight transpose + fp16
        __shared__ float tile[32][33];
        int z = bid >> 10, m = bid & 1023;
        const float* W = (z == 0) ? Wq : (z == 1) ? Wk : (z == 2) ? Wv : Wo;
        __half* Wt = g_wth + (size_t)z * 1024 * 1024;
        int bx = (m & 31) << 5, by = (m >> 5) << 5;
        int tx = t & 31, ty = t >> 5;
#pragma unroll
        for (int i = 0; i < 32; i += 8)
            tile[ty + i][tx] = W[(size_t)(by + ty + i) * 1024 + bx + tx];
        __syncthreads();
#pragma unroll
        for (int i = 0; i < 32; i += 8)
            Wt[(size_t)(bx + ty + i) * 1024 + by + tx] =
                __float2half(tile[tx][ty + i]);
        return;
    }
    if (bid < 4608) {  // ---- pos_emb -> fp16 (vec4)
        int i = (bid - 4096) * 256 + t;   // float4 index
        if (i < (Bc * Rc * 64) / 4) {
            float4 v = *(const float4*)(pos_emb + ((size_t)i << 2));
            __half2* d = (__half2*)(g_posh + ((size_t)i << 2));
            d[0] = __floats2half2_rn(v.x, v.y);
            d[1] = __floats2half2_rn(v.z, v.w);
        }
        return;
    }
    // ---- layernorm
    int row = bid - 4608;
    int b = row / Kc, r = row % Kc;
    const float* src = (r < Mc) ? (memory + ((size_t)b * Mc + r) * 1024)
                                : (hidden + ((size_t)b * Sc + (r - Mc)) * 1024);
    float4 v = *(const float4*)(src + (t << 2));
    float s = v.x + v.y + v.z + v.w;
    float sq = v.x * v.x + v.y * v.y + v.z * v.z + v.w * v.w;
#pragma unroll
    for (int m = 16; m; m >>= 1) {
        s  += __shfl_xor_sync(0xffffffffu, s, m);
        sq += __shfl_xor_sync(0xffffffffu, sq, m);
    }
    __shared__ float ss[8], ssq[8];
    int w = t >> 5, l = t & 31;
    if (l == 0) { ss[w] = s; ssq[w] = sq; }
    __syncthreads();
    if (w == 0) {
        float sv  = (l < 8) ? ss[l]  : 0.f;
        float sqv = (l < 8) ? ssq[l] : 0.f;
#pragma unroll
        for (int m = 4; m; m >>= 1) {
            sv  += __shfl_xor_sync(0xffffffffu, sv, m);
            sqv += __shfl_xor_sync(0xffffffffu, sqv, m);
        }
        if (l == 0) { ss[0] = sv; ssq[0] = sqv; }
    }
    __syncthreads();
    float mean = ss[0] * (1.f / 1024.f);
    float var  = ssq[0] * (1.f / 1024.f) - mean * mean;
    float inv  = rsqrtf(var + 1e-5f);
    float4 gv = *(const float4*)(gamma + (t << 2));
    float4 bv = *(const float4*)(beta + (t << 2));
    float o0 = (v.x - mean) * inv * gv.x + bv.x;
    float o1 = (v.y - mean) * inv * gv.y + bv.y;
    float o2 = (v.z - mean) * inv * gv.z + bv.z;
    float o3 = (v.w - mean) * inv * gv.w + bv.w;
    __half2* dsth = (__half2*)(g_clnh + (size_t)row * 1024) + (t << 1);
    dsth[0] = __floats2half2_rn(o0, o1);
    dsth[1] = __floats2half2_rn(o2, o3);
    if (r >= Mc) {
        *(float4*)(g_hln + ((size_t)b * Sc + (r - Mc)) * 1024 + (t << 2)) =
            make_float4(o0, o1, o2, o3);
    }
}

// ---------------------------------------------------------------------------
// fp16 GEMM body: C[128 x NC] = A[128x1024] @ Wt[NC x 1024]^T, BK=64,
// NC = NPW*32 (NPW=4 -> 128 cols, NPW=2 -> 64 cols).
// 3-stage ring / prefill 2 / ONE syncthreads per iter. 256 threads, 8 warps.
// ---------------------------------------------------------------------------
#define GASZ (128 * 72)

template <int MODE, int NPW>
__device__ __forceinline__ void gemm_body(const __half* __restrict__ A,
                                          const __half* __restrict__ Wt,
                                          __half* __restrict__ Ch,
                                          float* __restrict__ Cf,
                                          const float* __restrict__ res,
                                          __half* sm) {
    const int NC = NPW * 32;
    const int BSZ = NC * 72;
    const int STG = GASZ + BSZ;
    int t = threadIdx.x, lane = t & 31, w = t >> 5;
    int wm = (w >> 1) << 5, wn = (w & 1) * (NPW * 16);

    auto load_stage = [&](int ki) {
        __half* As = sm + (ki % 3) * STG;
        __half* Bs = As + GASZ;
        int k0 = ki << 6;
#pragma unroll
        for (int it = 0; it < 4; it++) {
            int e = t + (it << 8);
            int r = e >> 3, c = e & 7;
            cpa(sptr(As + r * 72 + (c << 3)), A + (size_t)r * 1024 + k0 + (c << 3));
        }
#pragma unroll
        for (int it = 0; it < NPW; it++) {
            int e = t + (it << 8);
            int r = e >> 3, c = e & 7;
            cpa(sptr(Bs + r * 72 + (c << 3)), Wt + (size_t)r * 1024 + k0 + (c << 3));
        }
    };

    load_stage(0); CP_COMMIT;
    load_stage(1); CP_COMMIT;

    float acc[2][2 * NPW][4];
#pragma unroll
    for (int mt = 0; mt < 2; mt++)
#pragma unroll
        for (int nt = 0; nt < 2 * NPW; nt++)
#pragma unroll
            for (int i = 0; i < 4; i++) acc[mt][nt][i] = 0.f;

    for (int i = 0; i < 16; i++) {
        CP_WAIT(1);
        __syncthreads();
        if (i + 2 < 16) load_stage(i + 2);
        CP_COMMIT;
        __half* As = sm + (i % 3) * STG;
        __half* Bs = As + GASZ;
#pragma unroll
        for (int kc = 0; kc < 4; kc++) {
            uint32_t am[2][4];
#pragma unroll
            for (int mt = 0; mt < 2; mt++)
                ldm4(am[mt], sptr(As + (wm + mt * 16 + (lane & 15)) * 72 +
                                  (kc << 4) + ((lane >> 4) << 3)));
#pragma unroll
            for (int np = 0; np < NPW; np++) {
                uint32_t bb[4];
                ldm4(bb, sptr(Bs + (wn + (np << 4) + (lane & 7) + ((lane >> 4) << 3)) * 72 +
                              (kc << 4) + (((lane >> 3) & 1) << 3)));
                mma16(acc[0][np * 2],     am[0], bb[0], bb[1]);
                mma16(acc[0][np * 2 + 1], am[0], bb[2], bb[3]);
                mma16(acc[1][np * 2],     am[1], bb[0], bb[1]);
                mma16(acc[1][np * 2 + 1], am[1], bb[2], bb[3]);
            }
        }
    }

    int R = lane >> 2, c2 = (lane & 3) << 1;
#pragma unroll
    for (int mt = 0; mt < 2; mt++) {
        int r0 = wm + mt * 16 + R, r1 = r0 + 8;
#pragma unroll
        for (int nt = 0; nt < 2 * NPW; nt++) {
            int c = wn + (nt << 3) + c2;
            if (MODE == 0) {
                *(__half2*)(Ch + (size_t)r0 * 1024 + c) =
                    __floats2half2_rn(acc[mt][nt][0], acc[mt][nt][1]);
                *(__half2*)(Ch + (size_t)r1 * 1024 + c) =
                    __floats2half2_rn(acc[mt][nt][2], acc[mt][nt][3]);
            } else {
                const float* rs0 = res + (size_t)r0 * 1024 + c;
                const float* rs1 = res + (size_t)r1 * 1024 + c;
                Cf[(size_t)r0 * 1024 + c]     = acc[mt][nt][0] + rs0[0];
                Cf[(size_t)r0 * 1024 + c + 1] = acc[mt][nt][1] + rs0[1];
                Cf[(size_t)r1 * 1024 + c]     = acc[mt][nt][2] + rs1[0];
                Cf[(size_t)r1 * 1024 + c + 1] = acc[mt][nt][3] + rs1[1];
            }
        }
    }
}

#define PROJ_SMEM_BYTES (3 * (GASZ + 128 * 72) * 2)
#define OUT_SMEM_BYTES  (3 * (GASZ + 64 * 72) * 2)

// Fused Q/K/V projection: grid (8, 80); y: [0,32) K, [32,64) V, [64,80) Q
__global__ __launch_bounds__(256, 2) void proj_tc() {
    extern __shared__ __align__(16) __half smh[];
    int y = blockIdx.y, col0 = blockIdx.x << 7;
    const __half* A;
    const __half* Wt;
    __half* Cb;
    if (y < 32) {
        A = g_clnh + (size_t)(y << 7) * 1024;
        Wt = g_wth + (1u << 20) + (size_t)col0 * 1024;
        Cb = g_kh + (size_t)(y << 7) * 1024 + col0;
    } else if (y < 64) {
        int yy = y - 32;
        A = g_clnh + (size_t)(yy << 7) * 1024;
        Wt = g_wth + (2u << 20) + (size_t)col0 * 1024;
        Cb = g_vh + (size_t)(yy << 7) * 1024 + col0;
    } else {
        int yy = y - 64;
        int b = yy >> 3, r0 = (yy & 7) << 7;
        A = g_clnh + ((size_t)(b * Kc + Mc) + r0) * 1024;
        Wt = g_wth + (size_t)col0 * 1024;
        Cb = g_qh + ((size_t)(b * Sc) + r0) * 1024 + col0;
    }
    gemm_body<0, 4>(A, Wt, Cb, nullptr, nullptr, smh);
}

// Output projection + residual: grid (16, 16), 128x64 tiles
__global__ __launch_bounds__(256, 2) void out_tc(float* __restrict__ out) {
    extern __shared__ __align__(16) __half smh[];
    int col0 = blockIdx.x << 6, row0 = blockIdx.y << 7;
    const __half* A = g_attnh + (size_t)row0 * 1024;
    const __half* Wt = g_wth + (3u << 20) + (size_t)col0 * 1024;
    const float* res = g_hln + (size_t)row0 * 1024 + col0;
    float* Cf = out + (size_t)row0 * 1024 + col0;
    gemm_body<1, 2>(A, Wt, nullptr, Cf, res, smh);
}

// ---------------------------------------------------------------------------
// fp16 flash attention (R12 base; softmax in log2 domain via folded scale).
// 128 threads / 4 warps / 64 query rows; qpos ring reuse; K,V double-buffered;
// pos pages triple-buffered; P in registers for PV; ONE sync+wait per k-tile.
// ---------------------------------------------------------------------------
#define AB_PQ 0
#define AB_K0 9216
#define AB_K1 18432
#define AB_V0 27648
#define AB_V1 36864
#define AB_P0 46080
#define AB_P1 55296
#define AB_P2 64512
#define AB_QP 73728
#define ATTN_SMEM_BYTES (AB_QP + 2 * 64 * 72 * 4)
#define SCL 0.04507909856f   // log2(e) / 32

__global__ __launch_bounds__(128) void attn_tc() {
    extern __shared__ __align__(16) char smb[];
    __half* Pq = (__half*)(smb + AB_PQ);
    __half* Kbuf[2] = {(__half*)(smb + AB_K0), (__half*)(smb + AB_K1)};
    __half* Vbuf[2] = {(__half*)(smb + AB_V0), (__half*)(smb + AB_V1)};
    __half* Pp[3] = {(__half*)(smb + AB_P0), (__half*)(smb + AB_P1),
                     (__half*)(smb + AB_P2)};
    float* Qpr = (float*)(smb + AB_QP);

    int t = threadIdx.x, lane = t & 31, w = t >> 5;
    int R = lane >> 2, c2 = (lane & 3) << 1;
    int qi = 15 - (int)blockIdx.x;
    int s0 = qi << 6;
    int bh = blockIdx.y, b = bh >> 4, h = bh & 15;

    const __half* qbase = g_qh + ((size_t)(b * Sc + s0)) * 1024 + h * 64;
    const __half* kbase = g_kh + ((size_t)b * Kc) * 1024 + h * 64;
    const __half* vbase = g_vh + ((size_t)b * Kc) * 1024 + h * 64;
    const __half* pbase = g_posh + (size_t)b * Rc * 64;
    int rr0base = 960 - s0;
    int ntiles = qi + 17;
    int dq0 = w * 16 + R, dq1 = dq0 + 8;

    for (int e = t; e < 512; e += 128) {
        int r = e >> 3, c = e & 7;
        cpa(sptr(Pq + r * 72 + (c << 3)), qbase + (size_t)r * 1024 + (c << 3));
        cpa(sptr(Pp[0] + r * 72 + (c << 3)),
            pbase + (size_t)(rr0base + r) * 64 + (c << 3));
        cpa(sptr(Pp[1] + r * 72 + (c << 3)),
            pbase + (size_t)(rr0base + 64 + r) * 64 + (c << 3));
        cpa(sptr(Kbuf[0] + r * 72 + (c << 3)), kbase + (size_t)r * 1024 + (c << 3));
        cpa(sptr(Vbuf[0] + r * 72 + (c << 3)), vbase + (size_t)r * 1024 + (c << 3));
    }
    CP_COMMIT;
    CP_WAIT(0);
    __syncthreads();

    uint32_t qf[4][4];
#pragma unroll
    for (int kc = 0; kc < 4; kc++)
        ldm4(qf[kc], sptr(Pq + (w * 16 + (lane & 15)) * 72 +
                          (kc << 4) + ((lane >> 4) << 3)));

    auto qpos_page = [&](__half* page, float* dst) {
#pragma unroll
        for (int np = 0; np < 4; np++) {
            float qa0[4] = {0.f, 0.f, 0.f, 0.f}, qa1[4] = {0.f, 0.f, 0.f, 0.f};
#pragma unroll
            for (int kc = 0; kc < 4; kc++) {
                uint32_t bb[4];
                ldm4(bb, sptr(page + ((np << 4) + (lane & 7) + ((lane >> 4) << 3)) * 72 +
                              (kc << 4) + (((lane >> 3) & 1) << 3)));
                mma16(qa0, qf[kc], bb[0], bb[1]);
                mma16(qa1, qf[kc], bb[2], bb[3]);
            }
            float* q0 = dst + dq0 * 72 + (np << 4);
            float* q1 = dst + dq1 * 72 + (np << 4);
            *(float2*)(q0 + c2)     = make_float2(qa0[0], qa0[1]);
            *(float2*)(q1 + c2)     = make_float2(qa0[2], qa0[3]);
            *(float2*)(q0 + 8 + c2) = make_float2(qa1[0], qa1[1]);
            *(float2*)(q1 + 8 + c2) = make_float2(qa1[2], qa1[3]);
        }
    };

    qpos_page(Pp[0], Qpr);

    float O[8][4];
#pragma unroll
    for (int nt = 0; nt < 8; nt++)
#pragma unroll
        for (int i = 0; i < 4; i++) O[nt][i] = 0.f;
    float m0 = -1e30f, m1 = -1e30f, l0 = 0.f, l1 = 0.f;

    for (int kt = 0; kt < ntiles; kt++) {
        int k0 = kt << 6;
        float* QpL = Qpr + (kt & 1) * (64 * 72);
        float* QpH = Qpr + ((kt + 1) & 1) * (64 * 72);
        __half* Ks = Kbuf[kt & 1];
        __half* Vs = Vbuf[kt & 1];

        if (kt) { CP_WAIT(0); __syncthreads(); }

        if (kt + 1 < ntiles) {
            __half* Pn = Pp[(kt + 2) % 3];
            __half* Kn = Kbuf[(kt + 1) & 1];
            __half* Vn = Vbuf[(kt + 1) & 1];
            int gp = rr0base + k0 + 128;
            int gk = k0 + 64;
            for (int e = t; e < 512; e += 128) {
                int r = e >> 3, c = e & 7;
                cpa(sptr(Pn + r * 72 + (c << 3)),
                    pbase + (size_t)(gp + r) * 64 + (c << 3));
                cpa(sptr(Kn + r * 72 + (c << 3)),
                    kbase + (size_t)(gk + r) * 1024 + (c << 3));
                cpa(sptr(Vn + r * 72 + (c << 3)),
                    vbase + (size_t)(gk + r) * 1024 + (c << 3));
            }
        }
        CP_COMMIT;

        qpos_page(Pp[(kt + 1) % 3], QpH);
        __syncwarp();

        float sc[8][4];
#pragma unroll
        for (int nt = 0; nt < 8; nt++)
#pragma unroll
            for (int i = 0; i < 4; i++) sc[nt][i] = 0.f;
#pragma unroll
        for (int np = 0; np < 4; np++) {
            int n0 = np << 4;
#pragma unroll
            for (int kc = 0; kc < 4; kc++) {
                uint32_t bb[4];
                ldm4(bb, sptr(Ks + (n0 + (lane & 7) + ((lane >> 4) << 3)) * 72 +
                              (kc << 4) + (((lane >> 3) & 1) << 3)));
                mma16(sc[np * 2],     qf[kc], bb[0], bb[1]);
                mma16(sc[np * 2 + 1], qf[kc], bb[2], bb[3]);
            }
        }

        // skew add + mask; scores scaled into log2 domain (log2e/32 folded)
#pragma unroll
        for (int nt = 0; nt < 8; nt++) {
#pragma unroll
            for (int j = 0; j < 2; j++) {
                int dk = (nt << 3) + c2 + j;
                int j0 = dk - dq0 + 63, j1 = dk - dq1 + 63;
                float p0 = (j0 < 64) ? QpL[dq0 * 72 + j0] : QpH[dq0 * 72 + j0 - 64];
                float p1 = (j1 < 64) ? QpL[dq1 * 72 + j1] : QpH[dq1 * 72 + j1 - 64];
                bool mk0 = (k0 + dk) > (s0 + dq0 + Mc);
                bool mk1 = (k0 + dk) > (s0 + dq1 + Mc);
                sc[nt][j]     = mk0 ? -1e30f : (sc[nt][j] + p0) * SCL;
                sc[nt][2 + j] = mk1 ? -1e30f : (sc[nt][2 + j] + p1) * SCL;
            }
        }

        // online softmax in log2 domain; P emitted into mma A-fragments
        float mx0 = -1e30f, mx1 = -1e30f;
#pragma unroll
        for (int nt = 0; nt < 8; nt++) {
            mx0 = fmaxf(mx0, fmaxf(sc[nt][0], sc[nt][1]));
            mx1 = fmaxf(mx1, fmaxf(sc[nt][2], sc[nt][3]));
        }
        mx0 = fmaxf(mx0, __shfl_xor_sync(0xffffffffu, mx0, 1));
        mx0 = fmaxf(mx0, __shfl_xor_sync(0xffffffffu, mx0, 2));
        mx1 = fmaxf(mx1, __shfl_xor_sync(0xffffffffu, mx1, 1));
        mx1 = fmaxf(mx1, __shfl_xor_sync(0xffffffffu, mx1, 2));
        float mn0 = fmaxf(m0, mx0), mn1 = fmaxf(m1, mx1);
        float al0 = exp2f(m0 - mn0), al1 = exp2f(m1 - mn1);
        m0 = mn0; m1 = mn1;
        float su0 = 0.f, su1 = 0.f;
        uint32_t ph[4][4];
#pragma unroll
        for (int nt = 0; nt < 8; nt++) {
            float p0 = exp2f(sc[nt][0] - mn0), p1 = exp2f(sc[nt][1] - mn0);
            float p2 = exp2f(sc[nt][2] - mn1), p3 = exp2f(sc[nt][3] - mn1);
            su0 += p0 + p1; su1 += p2 + p3;
            __half2 h01 = __floats2half2_rn(p0, p1);
            __half2 h23 = __floats2half2_rn(p2, p3);
            int kc = nt >> 1, hi = (nt & 1) << 1;
            ph[kc][hi]     = *(uint32_t*)&h01;
            ph[kc][hi + 1] = *(uint32_t*)&h23;
        }
        su0 += __shfl_xor_sync(0xffffffffu, su0, 1);
        su0 += __shfl_xor_sync(0xffffffffu, su0, 2);
        su1 += __shfl_xor_sync(0xffffffffu, su1, 1);
        su1 += __shfl_xor_sync(0xffffffffu, su1, 2);
        l0 = l0 * al0 + su0; l1 = l1 * al1 + su1;
#pragma unroll
        for (int nt = 0; nt < 8; nt++) {
            O[nt][0] *= al0; O[nt][1] *= al0;
            O[nt][2] *= al1; O[nt][3] *= al1;
        }

#pragma unroll
        for (int kc = 0; kc < 4; kc++) {
#pragma unroll
            for (int np = 0; np < 4; np++) {
                uint32_t bb[4];
                ldm4t(bb, sptr(Vs + ((kc << 4) + (lane & 7) + (((lane >> 3) & 1) << 3)) * 72 +
                               (np << 4) + ((lane >> 4) << 3)));
                mma16(O[np * 2],     ph[kc], bb[0], bb[1]);
                mma16(O[np * 2 + 1], ph[kc], bb[2], bb[3]);
            }
        }
    }

    float i0 = 1.f / l0, i1 = 1.f / l1;
    __half* obase = g_attnh + ((size_t)(b * Sc + s0)) * 1024 + h * 64;
#pragma unroll
    for (int nt = 0; nt < 8; nt++) {
        int c = (nt << 3) + c2;
        *(__half2*)(obase + (size_t)dq0 * 1024 + c) =
            __floats2half2_rn(O[nt][0] * i0, O[nt][1] * i0);
        *(__half2*)(obase + (size_t)dq1 * 1024 + c) =
            __floats2half2_rn(O[nt][2] * i1, O[nt][3] * i1);
    }
}

// ---------------------------------------------------------------------------
extern "C" void kernel_launch(void* const* d_in, const int* in_sizes, int n_in,
                              void* d_out, int out_size) {
    const float* hidden  = (const float*)d_in[0];
    const float* pos_emb = (const float*)d_in[1];
    const float* memory  = (const float*)d_in[2];
    // d_in[3] = mask (bool) — recomputed analytically
    const float* Wq = (const float*)d_in[4];
    const float* Wk = (const float*)d_in[5];
    const float* Wv = (const float*)d_in[6];
    const float* Wo = (const float*)d_in[7];
    const float* gamma = (const float*)d_in[8];
    const float* beta  = (const float*)d_in[9];
    float* out = (float*)d_out;

    fused_pre<<<8704, 256>>>(hidden, memory, gamma, beta, Wq, Wk, Wv, Wo,
                             pos_emb);

    cudaFuncSetAttribute(proj_tc, cudaFuncAttributeMaxDynamicSharedMemorySize,
                         PROJ_SMEM_BYTES);
    cudaFuncSetAttribute(out_tc, cudaFuncAttributeMaxDynamicSharedMemorySize,
                         OUT_SMEM_BYTES);
    proj_tc<<<dim3(8, 80), 256, PROJ_SMEM_BYTES>>>();

    cudaFuncSetAttribute(attn_tc, cudaFuncAttributeMaxDynamicSharedMemorySize,
                         ATTN_SMEM_BYTES);
    attn_tc<<<dim3(16, Bc * Hc), 128, ATTN_SMEM_BYTES>>>();

    out_tc<<<dim3(16, 16), 256, OUT_SMEM_BYTES>>>(out);
}